// round 2
// baseline (speedup 1.0000x reference)
#include <cuda_runtime.h>
#include <cuda_bf16.h>
#include <cstdint>

// Problem constants (fixed by the reference)
#define NNODES 50000
#define FDIM   64
#define NEDGES 800000

// Scratch (static device allocation — allowed). 16B-aligned for v4 red.
__device__ __align__(16) float g_agg[(size_t)NNODES * FDIM];
__device__ float g_deg[NNODES];
__device__ int   g_idx_is_i32;   // 1 if edge_index arrives as int32, 0 if int64

// ---------------------------------------------------------------------------
// Kernel 0: detect index dtype. If the buffer holds int64 values < 2^31,
// every odd 32-bit word is zero. For int32 data those words are real indices
// (random in [0, 50000)), so 256 consecutive zeros is impossible in practice.
// ---------------------------------------------------------------------------
__global__ void detect_kernel(const int* __restrict__ ei32) {
    unsigned v = 0;
    for (int k = threadIdx.x; k < 256; k += 32)
        v |= (unsigned)ei32[2 * k + 1];
#pragma unroll
    for (int off = 16; off > 0; off >>= 1)
        v |= __shfl_xor_sync(0xffffffffu, v, off);
    if (threadIdx.x == 0)
        g_idx_is_i32 = (v != 0u) ? 1 : 0;
}

// ---------------------------------------------------------------------------
// Kernel 1: zero the scratch buffers
// ---------------------------------------------------------------------------
__global__ void zero_kernel() {
    int i = blockIdx.x * blockDim.x + threadIdx.x;
    if (i < (NNODES * FDIM) / 4)
        ((float4*)g_agg)[i] = make_float4(0.f, 0.f, 0.f, 0.f);
    if (i < NNODES)
        g_deg[i] = 0.f;
}

// Vector reduction: one 16B red op instead of 4 scalar atomics (sm_90+)
__device__ __forceinline__ void red_add_v4(float* addr, float4 v) {
    asm volatile("red.global.add.v4.f32 [%0], {%1, %2, %3, %4};"
                 :: "l"(addr), "f"(v.x), "f"(v.y), "f"(v.z), "f"(v.w)
                 : "memory");
}

// ---------------------------------------------------------------------------
// Kernel 2: edge scatter. 16 threads per edge, each handles one float4 lane.
//   agg[row] += x[col]; deg[row] += 1 (lane 0)
// ---------------------------------------------------------------------------
__global__ void scatter_kernel(const float* __restrict__ x,
                               const void* __restrict__ ei_raw) {
    long long t = (long long)blockIdx.x * blockDim.x + threadIdx.x;
    int e = (int)(t >> 4);
    int j = (int)(t & 15);
    if (e >= NEDGES) return;

    int row, col;
    if (g_idx_is_i32) {
        const int* ei = (const int*)ei_raw;
        row = ei[e];
        col = ei[NEDGES + e];
    } else {
        const long long* ei = (const long long*)ei_raw;
        row = (int)ei[e];
        col = (int)ei[NEDGES + e];
    }
    // Defensive: never fault on a bad index.
    if ((unsigned)row >= NNODES || (unsigned)col >= NNODES) return;

    float4 v = ((const float4*)(x + (size_t)col * FDIM))[j];
    red_add_v4(g_agg + (size_t)row * FDIM + j * 4, v);

    if (j == 0)
        atomicAdd(&g_deg[row], 1.0f);
}

// ---------------------------------------------------------------------------
// Kernel 3: fused scale (1/deg) + linear (agg @ W^T + b)
// blockDim = (64, 4). W transposed into padded shared; persistent grid-stride.
// ---------------------------------------------------------------------------
__global__ void __launch_bounds__(256)
linear_kernel(const float* __restrict__ W,
              const float* __restrict__ b,
              float* __restrict__ out) {
    __shared__ float Ws[64 * 65];   // Ws[k*65 + o] = W[o][k]
    __shared__ float as[4][64];

    int tx  = threadIdx.x;          // output column o
    int ty  = threadIdx.y;          // node slot
    int tid = ty * 64 + tx;

    for (int i = tid; i < 64 * 64; i += 256) {
        int o = i >> 6;
        int k = i & 63;
        Ws[k * 65 + o] = W[i];
    }
    float bo = b[tx];
    __syncthreads();

    for (int base = blockIdx.x * 4; base < NNODES; base += gridDim.x * 4) {
        int node = base + ty;
        if (node < NNODES) {
            float inv = 1.0f / (g_deg[node] + 1e-6f);
            as[ty][tx] = g_agg[(size_t)node * FDIM + tx] * inv;
        }
        __syncthreads();
        if (node < NNODES) {
            float acc = bo;
#pragma unroll
            for (int k = 0; k < 64; k++)
                acc = fmaf(as[ty][k], Ws[k * 65 + tx], acc);
            out[(size_t)node * FDIM + tx] = acc;
        }
        __syncthreads();
    }
}

// ---------------------------------------------------------------------------
// Launch
// ---------------------------------------------------------------------------
extern "C" void kernel_launch(void* const* d_in, const int* in_sizes, int n_in,
                              void* d_out, int out_size) {
    const float* x  = (const float*)d_in[0];
    const void*  ei = d_in[1];
    const float* W  = (const float*)d_in[2];
    const float* b  = (const float*)d_in[3];
    float*       out = (float*)d_out;

    detect_kernel<<<1, 32>>>((const int*)ei);

    {
        int n = (NNODES * FDIM) / 4;   // 800000 (also covers deg)
        zero_kernel<<<(n + 255) / 256, 256>>>();
    }
    {
        long long work = (long long)NEDGES * 16;
        scatter_kernel<<<(int)((work + 255) / 256), 256>>>(x, ei);
    }
    {
        dim3 threads(64, 4);
        linear_kernel<<<1184, threads>>>(W, b, out);
    }
}